// round 3
// baseline (speedup 1.0000x reference)
#include <cuda_runtime.h>
#include <cuda_bf16.h>
#include <cstdint>
#include <cstddef>

#define BATCH 4096
#define DIM   1024
#define TDICT 32768
#define TOPK  64
#define CAP   4096
#define NCAND 128
#define SBIN  128

#define BM 128
#define BN 128
#define KC 64
#define NCHUNK (DIM / KC)   // 16

// ------------------------- device scratch (no allocation allowed) -------------------------
__device__ __nv_bfloat16 g_xb[(size_t)BATCH * DIM];      // bf16 centered x          (8 MB)
__device__ float         g_xc[(size_t)BATCH * DIM];      // fp32 centered x          (16 MB)
__device__ __nv_bfloat16 g_Wb[(size_t)TDICT * DIM];      // bf16 W_enc^T             (64 MB)
__device__ float         g_WT[(size_t)TDICT * DIM];      // fp32 W_enc^T             (128 MB)
__device__ __nv_bfloat16 g_acts[(size_t)BATCH * TDICT];  // approx relu acts         (256 MB)
__device__ int   g_cand_idx[(size_t)BATCH * CAP];        // 64 MB
__device__ int   g_cand_cnt[BATCH];
__device__ float g_top_val[BATCH * TOPK];
__device__ int   g_top_idx[BATCH * TOPK];

// ------------------------- helpers -------------------------
__device__ __forceinline__ uint32_t smem_u32(const void* p) {
    uint32_t a;
    asm("{ .reg .u64 t; cvta.to.shared.u64 t, %1; cvt.u32.u64 %0, t; }" : "=r"(a) : "l"(p));
    return a;
}

#define SWZ128(o) ((o) ^ (((o) >> 3) & 0x70))

__device__ __forceinline__ void ldm_x4(uint32_t* r, uint32_t addr) {
    asm volatile("ldmatrix.sync.aligned.m8n8.x4.shared.b16 {%0,%1,%2,%3}, [%4];"
                 : "=r"(r[0]), "=r"(r[1]), "=r"(r[2]), "=r"(r[3]) : "r"(addr));
}
__device__ __forceinline__ void ldm_x2(uint32_t* r, uint32_t addr) {
    asm volatile("ldmatrix.sync.aligned.m8n8.x2.shared.b16 {%0,%1}, [%2];"
                 : "=r"(r[0]), "=r"(r[1]) : "r"(addr));
}
__device__ __forceinline__ void mma_16816(float* c, const uint32_t* a, const uint32_t* b) {
    asm volatile("mma.sync.aligned.m16n8k16.row.col.f32.bf16.bf16.f32 "
                 "{%0,%1,%2,%3}, {%4,%5,%6,%7}, {%8,%9}, {%0,%1,%2,%3};"
                 : "+f"(c[0]), "+f"(c[1]), "+f"(c[2]), "+f"(c[3])
                 : "r"(a[0]), "r"(a[1]), "r"(a[2]), "r"(a[3]), "r"(b[0]), "r"(b[1]));
}

// ------------------------- kernel 1: x_cent = x - b_dec (fp32 + bf16) -------------------------
__global__ void __launch_bounds__(256) prep_x_kernel(const float* __restrict__ x,
                                                     const float* __restrict__ b_dec) {
    int i = blockIdx.x * 256 + threadIdx.x;
    float v = x[i] - b_dec[i & (DIM - 1)];
    g_xc[i] = v;
    g_xb[i] = __float2bfloat16_rn(v);
}

// ------------------------- kernel 2: W_enc [1024,32768] -> W^T [32768,1024] ----------
__global__ void __launch_bounds__(256) transpose_kernel(const float* __restrict__ W_enc) {
    __shared__ float tile[32][33];
    const int jt = blockIdx.x * 32;   // dict dim
    const int kt = blockIdx.y * 32;   // input dim
    const int tx = threadIdx.x, ty = threadIdx.y;  // 32 x 8
#pragma unroll
    for (int i = 0; i < 4; i++)
        tile[ty + i * 8][tx] = W_enc[(size_t)(kt + ty + i * 8) * TDICT + jt + tx];
    __syncthreads();
#pragma unroll
    for (int i = 0; i < 4; i++) {
        int j = jt + ty + i * 8;
        float v = tile[tx][ty + i * 8];
        g_WT[(size_t)j * DIM + kt + tx] = v;
        g_Wb[(size_t)j * DIM + kt + tx] = __float2bfloat16_rn(v);
    }
}

// ------------------------- kernel 3: bf16 mma.sync GEMM 128x128, double buffered -------------
__device__ __forceinline__ void load_tile_pair(uint32_t sb, uint32_t offA, uint32_t offB,
                                               const __nv_bfloat16* A, const __nv_bfloat16* B,
                                               int kc, int tid) {
#pragma unroll
    for (int t = 0; t < 4; t++) {
        int task = tid + t * 256;     // 0..1023
        int r = task >> 3, c = task & 7;
        const void* srcA = A + (size_t)r * DIM + kc * KC + c * 8;
        const void* srcB = B + (size_t)r * DIM + kc * KC + c * 8;
        uint32_t sw = SWZ128((uint32_t)(r * 128 + c * 16));
        asm volatile("cp.async.cg.shared.global [%0], [%1], 16;" :: "r"(sb + offA + sw), "l"(srcA));
        asm volatile("cp.async.cg.shared.global [%0], [%1], 16;" :: "r"(sb + offB + sw), "l"(srcB));
    }
    asm volatile("cp.async.commit_group;" ::: "memory");
}

__global__ void __launch_bounds__(256, 2) gemm_kernel(const float* __restrict__ b_enc) {
    extern __shared__ char sm[];
    const uint32_t sb = smem_u32(sm);
    const int tid = threadIdx.x;
    const int wid = tid >> 5, lane = tid & 31;
    const int mbase = blockIdx.x * BM;   // batch tile
    const int nbase = blockIdx.y * BN;   // dict tile
    const int warp_m = wid & 1;          // 0..1 -> 64 rows each
    const int warp_n = wid >> 1;         // 0..3 -> 32 cols each

    const uint32_t OFF_A[2] = {0u, 32768u};
    const uint32_t OFF_B[2] = {16384u, 49152u};

    float acc[4][4][4];
#pragma unroll
    for (int mi = 0; mi < 4; mi++)
#pragma unroll
        for (int ni = 0; ni < 4; ni++)
#pragma unroll
            for (int r = 0; r < 4; r++) acc[mi][ni][r] = 0.f;

    const __nv_bfloat16* Abase = g_xb + (size_t)mbase * DIM;
    const __nv_bfloat16* Bbase = g_Wb + (size_t)nbase * DIM;

    // per-lane ldmatrix row/col components
    const int rowA = warp_m * 64 + (lane & 15);
    const int caA  = (lane & 16) ? 8 : 0;
    const int l16  = lane & 15;
    const int rowB = warp_n * 32 + (l16 & 7);
    const int caB  = (l16 & 8) ? 8 : 0;

    load_tile_pair(sb, OFF_A[0], OFF_B[0], Abase, Bbase, 0, tid);

    for (int kc = 0; kc < NCHUNK; kc++) {
        const int p = kc & 1;
        if (kc + 1 < NCHUNK) {
            load_tile_pair(sb, OFF_A[p ^ 1], OFF_B[p ^ 1], Abase, Bbase, kc + 1, tid);
            asm volatile("cp.async.wait_group 1;" ::: "memory");
        } else {
            asm volatile("cp.async.wait_group 0;" ::: "memory");
        }
        __syncthreads();

        const uint32_t baseA = sb + OFF_A[p];
        const uint32_t baseB = sb + OFF_B[p];
#pragma unroll
        for (int kk = 0; kk < 4; kk++) {
            uint32_t a[4][4], b[4][2];
#pragma unroll
            for (int mi = 0; mi < 4; mi++)
                ldm_x4(a[mi], baseA + SWZ128((uint32_t)((rowA + mi * 16) * 128 + (kk * 16 + caA) * 2)));
#pragma unroll
            for (int ni = 0; ni < 4; ni++)
                ldm_x2(b[ni], baseB + SWZ128((uint32_t)((rowB + ni * 8) * 128 + (kk * 16 + caB) * 2)));
#pragma unroll
            for (int mi = 0; mi < 4; mi++)
#pragma unroll
                for (int ni = 0; ni < 4; ni++)
                    mma_16816(acc[mi][ni], a[mi], b[ni]);
        }
        __syncthreads();
    }

    // epilogue: +b_enc, relu, bf16 store
    const int m0 = mbase + warp_m * 64;
    const int n0 = nbase + warp_n * 32;
    const int r0 = lane >> 2, c0 = (lane & 3) * 2;
#pragma unroll
    for (int ni = 0; ni < 4; ni++) {
        const int col = n0 + ni * 8 + c0;
        const float be0 = b_enc[col], be1 = b_enc[col + 1];
#pragma unroll
        for (int mi = 0; mi < 4; mi++) {
            const int row = m0 + mi * 16 + r0;
            float v0 = fmaxf(acc[mi][ni][0] + be0, 0.f);
            float v1 = fmaxf(acc[mi][ni][1] + be1, 0.f);
            *(__nv_bfloat162*)(g_acts + (size_t)row * TDICT + col) = __floats2bfloat162_rn(v0, v1);
            float v2 = fmaxf(acc[mi][ni][2] + be0, 0.f);
            float v3 = fmaxf(acc[mi][ni][3] + be1, 0.f);
            *(__nv_bfloat162*)(g_acts + (size_t)(row + 8) * TDICT + col) = __floats2bfloat162_rn(v2, v3);
        }
    }
}

// ------------------------- kernel 4: per-row threshold + candidate gather -------------------------
// Histogram only values >= 2.0 (bits >= 0x4000); 128 bins of 8 bf16 codes covering [2, 32).
__global__ void __launch_bounds__(256) select_kernel() {
    const int row = blockIdx.x, tid = threadIdx.x;
    const uint4* arow = (const uint4*)(g_acts + (size_t)row * TDICT);
    __shared__ int hist[SBIN];
    __shared__ int sa[SBIN];
    __shared__ int Tbits, cnt;
    if (tid < SBIN) hist[tid] = 0;
    if (tid == 0) cnt = 0;
    __syncthreads();

    for (int i = tid; i < TDICT / 8; i += 256) {
        uint4 v = arow[i];
        uint32_t w[4] = {v.x, v.y, v.z, v.w};
#pragma unroll
        for (int s = 0; s < 4; s++)
#pragma unroll
            for (int h = 0; h < 2; h++) {
                uint32_t u = (w[s] >> (h * 16)) & 0xFFFFu;
                if (u >= 0x4000u && u < 0x8000u) {
                    int b = (int)((u - 0x4000u) >> 3);
                    if (b > SBIN - 1) b = SBIN - 1;
                    atomicAdd(&hist[b], 1);
                }
            }
    }
    __syncthreads();
    if (tid < SBIN) sa[tid] = hist[tid];
    __syncthreads();
    // suffix sum: sa[b] = count(bin >= b)
    for (int off = 1; off < SBIN; off <<= 1) {
        int v = (tid < SBIN && tid + off < SBIN) ? sa[tid + off] : 0;
        __syncthreads();
        if (tid < SBIN) sa[tid] += v;
        __syncthreads();
    }
    if (tid == 0) {
        int T;
        if (sa[0] < NCAND) {
            T = 1;  // take all positives
        } else {
            int b = 0;
            for (int i = SBIN - 1; i >= 0; i--)
                if (sa[i] >= NCAND) { b = i; break; }
            T = 0x4000 + (b << 3);
        }
        Tbits = T;
    }
    __syncthreads();
    const uint32_t T = (uint32_t)Tbits;
    for (int i = tid; i < TDICT / 8; i += 256) {
        uint4 v = arow[i];
        uint32_t w[4] = {v.x, v.y, v.z, v.w};
#pragma unroll
        for (int s = 0; s < 4; s++)
#pragma unroll
            for (int h = 0; h < 2; h++) {
                uint32_t u = (w[s] >> (h * 16)) & 0xFFFFu;
                if (u >= T && u < 0x8000u) {
                    int p = atomicAdd(&cnt, 1);
                    if (p < CAP) g_cand_idx[(size_t)row * CAP + p] = i * 8 + s * 2 + h;
                }
            }
    }
    __syncthreads();
    if (tid == 0) g_cand_cnt[row] = (cnt < CAP) ? cnt : CAP;
}

// ------------------------- kernel 5: exact fp32 rescore + bitonic top-64 -------------------------
__global__ void __launch_bounds__(256) rescore_kernel(const float* __restrict__ b_enc) {
    const int row = blockIdx.x, tid = threadIdx.x;
    const int wid = tid >> 5, lane = tid & 31;
    __shared__ float xs[DIM];
    __shared__ float vals[CAP];
    __shared__ int   idxs[CAP];
    for (int t = tid; t < DIM; t += 256) xs[t] = g_xc[(size_t)row * DIM + t];
    for (int c = tid; c < CAP; c += 256) { vals[c] = 0.f; idxs[c] = 0; }
    __syncthreads();
    const int n = g_cand_cnt[row];
    for (int c = wid; c < n; c += 8) {
        const int j = g_cand_idx[(size_t)row * CAP + c];
        const float4* wr = (const float4*)(g_WT + (size_t)j * DIM);
        float s = 0.f;
        for (int t = lane; t < DIM / 4; t += 32) {
            float4 f = wr[t];
            s += f.x * xs[4 * t] + f.y * xs[4 * t + 1] + f.z * xs[4 * t + 2] + f.w * xs[4 * t + 3];
        }
#pragma unroll
        for (int o = 16; o > 0; o >>= 1) s += __shfl_xor_sync(0xFFFFFFFFu, s, o);
        if (lane == 0) { vals[c] = fmaxf(s + b_enc[j], 0.f); idxs[c] = j; }
    }
    __syncthreads();
    int S = 256;
    while (S < n && S < CAP) S <<= 1;
    for (int k = 2; k <= S; k <<= 1)
        for (int jj = k >> 1; jj > 0; jj >>= 1) {
            for (int i = tid; i < S; i += 256) {
                int l = i ^ jj;
                if (l > i) {
                    float vi = vals[i], vl = vals[l];
                    bool up = ((i & k) == 0);
                    if ((vi > vl) == up) {   // ascending
                        vals[i] = vl; vals[l] = vi;
                        int t = idxs[i]; idxs[i] = idxs[l]; idxs[l] = t;
                    }
                }
            }
            __syncthreads();
        }
    if (tid < TOPK) {
        g_top_val[row * TOPK + tid] = vals[S - TOPK + tid];
        g_top_idx[row * TOPK + tid] = idxs[S - TOPK + tid];
    }
}

// ------------------------- kernel 6: nested group-wise sparse decode -------------------------
__global__ void __launch_bounds__(256) decode_kernel(const float* __restrict__ W_dec,
                                                     const float* __restrict__ b_dec,
                                                     float* __restrict__ out) {
    const int row = blockIdx.x, tid = threadIdx.x;
    __shared__ float sv[TOPK];
    __shared__ int   si[TOPK];
    if (tid < TOPK) {
        sv[tid] = g_top_val[row * TOPK + tid];
        si[tid] = g_top_idx[row * TOPK + tid];
    }
    __syncthreads();
    float4 acc = ((const float4*)b_dec)[tid];
    const int lo[3] = {0, 2048, 8192};
    const int hi[3] = {2048, 8192, 32768};
#pragma unroll
    for (int g = 0; g < 3; g++) {
        for (int t = 0; t < TOPK; t++) {
            const int j = si[t];
            const float v = sv[t];
            if (v > 0.f && j >= lo[g] && j < hi[g]) {
                float4 w = ((const float4*)(W_dec + (size_t)j * DIM))[tid];
                acc.x += v * w.x; acc.y += v * w.y; acc.z += v * w.z; acc.w += v * w.w;
            }
        }
        ((float4*)(out + (size_t)g * BATCH * DIM + (size_t)row * DIM))[tid] = acc;
    }
}

// ------------------------- launch -------------------------
extern "C" void kernel_launch(void* const* d_in, const int* in_sizes, int n_in,
                              void* d_out, int out_size) {
    const float* x     = (const float*)d_in[0];
    const float* W_enc = (const float*)d_in[1];
    const float* b_enc = (const float*)d_in[2];
    const float* W_dec = (const float*)d_in[3];
    const float* b_dec = (const float*)d_in[4];
    float* out = (float*)d_out;

    cudaFuncSetAttribute(gemm_kernel, cudaFuncAttributeMaxDynamicSharedMemorySize, 65536);

    prep_x_kernel<<<BATCH * DIM / 256, 256>>>(x, b_dec);
    transpose_kernel<<<dim3(TDICT / 32, DIM / 32), dim3(32, 8)>>>(W_enc);
    gemm_kernel<<<dim3(BATCH / BM, TDICT / BN), 256, 65536>>>(b_enc);
    select_kernel<<<BATCH, 256>>>();
    rescore_kernel<<<BATCH, 256>>>(b_enc);
    decode_kernel<<<BATCH, 256>>>(W_dec, b_dec, out);
}